// round 11
// baseline (speedup 1.0000x reference)
#include <cuda_runtime.h>
#include <cuda_bf16.h>
#include <math.h>

// Problem constants
#define FD      128
#define K       15
#define FS      160
#define OV      40
#define NF      500
#define BATCH   32
#define NTOT    (NF * FS)          // 80000 samples per batch row
#define NFR     (BATCH * NF)       // 16000 frames total

// C = ln(10)/20 ; LOG_GAIN_LIMIT = 10*C ; GAIN_A = 6*C ; GAIN_B = 0
#define LOG_GAIN_LIMIT 1.1512925464970229f
#define GAIN_A         0.6907755278982137f
#define PI_F           3.14159265358979323846f

// Per-frame coefficients: [0..14] = taps * gain / ||k|| (folded), [15] = ggain
__device__ __align__(16) float g_coef[NFR * 16];

// 15-tap dot from a 19-float window and 4 packed float4 coefficient regs
#define CONV15(xw, i, A, B, Cc, D) \
  ( xw[(i)+0]*A.x  + xw[(i)+1]*A.y  + xw[(i)+2]*A.z  + xw[(i)+3]*A.w  \
  + xw[(i)+4]*B.x  + xw[(i)+5]*B.y  + xw[(i)+6]*B.z  + xw[(i)+7]*B.w  \
  + xw[(i)+8]*Cc.x + xw[(i)+9]*Cc.y + xw[(i)+10]*Cc.z+ xw[(i)+11]*Cc.w\
  + xw[(i)+12]*D.x + xw[(i)+13]*D.y + xw[(i)+14]*D.z )

// ---------------------------------------------------------------------------
// Kernel A (dots): block = 64 threads (2 warps), 16 frames per warp.
// Weights (17x128) staged in shared ONCE per block -> each frame's 17 dots
// cost broadcast-LDS instead of per-warp global re-reads (16x traffic cut).
// 2 lanes per frame (64 d's each), 17 register accumulators, 1 shuffle level,
// fully in-thread epilogue (norm/exp/tanh), float4 coefficient stores.
// ---------------------------------------------------------------------------
__global__ __launch_bounds__(64)
void dots_kernel(const float* __restrict__ features,
                 const float* __restrict__ ck_w, const float* __restrict__ ck_b,
                 const float* __restrict__ fg_w, const float* __restrict__ fg_b,
                 const float* __restrict__ gg_w, const float* __restrict__ gg_b)
{
    __shared__ __align__(16) float s_w[17 * 128];        // 8.5 KB
    __shared__ __align__(16) float s_f[2][16 * 132];     // 16 frames, pad 132
    const int tid  = threadIdx.x;
    const int lane = tid & 31;
    const int warp = tid >> 5;
    const int fr0  = blockIdx.x * 32 + warp * 16;        // grid = NFR/32 = 500

    // stage weights: rows 0..14 = ck_w (480 f4), 15 = fg_w, 16 = gg_w
    for (int o4 = tid; o4 < 544; o4 += 64) {
        float4 v;
        if (o4 < 480)      v = __ldg((const float4*)ck_w + o4);
        else if (o4 < 512) v = __ldg((const float4*)fg_w + (o4 - 480));
        else               v = __ldg((const float4*)gg_w + (o4 - 512));
        *(float4*)(s_w + o4 * 4) = v;
    }
    // stage this warp's 16x128 feature tile with pad-132 swizzle
    {
        const float4* src = (const float4*)(features + (size_t)fr0 * FD);
        float* dst = s_f[warp];
        #pragma unroll
        for (int j = 0; j < 16; j++) {
            const int o4 = j * 32 + lane;
            const float4 v = __ldg(src + o4);
            const int o = o4 * 4;
            *(float4*)(dst + o + 4 * (o >> 7)) = v;      // frame stride 132
        }
    }
    __syncthreads();

    const int myf  = lane >> 1;     // frame within tile
    const int half = lane & 1;      // d-half (64 features)
    const float* fb = s_f[warp] + myf * 132 + half * 64;
    const float* wb = s_w + half * 64;

    float acc[17];
    #pragma unroll
    for (int r = 0; r < 17; r++) acc[r] = 0.f;

    #pragma unroll 4
    for (int q = 0; q < 16; q++) {
        const float4 f4 = *(const float4*)(fb + q * 4);
        #pragma unroll
        for (int r = 0; r < 17; r++) {
            const float4 w4 = *(const float4*)(wb + r * 128 + q * 4);
            acc[r] += f4.x*w4.x + f4.y*w4.y + f4.z*w4.z + f4.w*w4.w;
        }
    }
    #pragma unroll
    for (int r = 0; r < 17; r++)
        acc[r] += __shfl_xor_sync(0xffffffffu, acc[r], 1);

    if (half == 0) {
        const int fr = fr0 + myf;
        float d[15], ss = 0.f;
        #pragma unroll
        for (int r = 0; r < 15; r++) {
            d[r] = acc[r] + __ldg(ck_b + r);
            ss += d[r] * d[r];
        }
        const float fgd = acc[15] + __ldg(fg_b);
        const float ggd = acc[16] + __ldg(gg_b);
        const float gs  = __expf(LOG_GAIN_LIMIT - fmaxf(fgd, 0.f))
                        / (1e-6f + sqrtf(ss));
        const float gg  = __expf(GAIN_A * tanhf(ggd));
        float4* dst = (float4*)(g_coef + (size_t)fr * 16);
        dst[0] = make_float4(d[0]*gs,  d[1]*gs,  d[2]*gs,  d[3]*gs);
        dst[1] = make_float4(d[4]*gs,  d[5]*gs,  d[6]*gs,  d[7]*gs);
        dst[2] = make_float4(d[8]*gs,  d[9]*gs,  d[10]*gs, d[11]*gs);
        dst[3] = make_float4(d[12]*gs, d[13]*gs, d[14]*gs, gg);
    }
}

// ---------------------------------------------------------------------------
// Kernel B (fir): one warp per FRAME PAIR (f0 even, f1 = f0+1), 256-thr blocks.
// Shared per warp (776 floats):
//   [  0..214)  xc0 : x[base0-lag0 ..]   (214 = frame0 conv + frame1 prev-tail)
//   [216..390)  xc1 : x[base0+160-lag1 ..]  frame1 conv window
//   [392..446)  xp0 : x[base0-lagp ..]      frame0 prev-tail window
//   [448..768)  pt  : x[f0*FS .. +320)      pass-through, both frames
// Coefficients read as uniform __ldg float4 (no shared bounce).
// ---------------------------------------------------------------------------
__global__ __launch_bounds__(256)
void fir_kernel(const float* __restrict__ x,
                const int*   __restrict__ lags,
                float*       __restrict__ out)
{
    __shared__ __align__(16) float sh[8][776];
    const int lane = threadIdx.x & 31;
    const int warp = threadIdx.x >> 5;
    const int g    = blockIdx.x * 8 + warp;    // pair index, grid = NFR/16 = 1000
    const int fr0  = g * 2;
    const int b    = g / 250;
    const int f0   = fr0 - b * NF;             // even frame index in [0, 500)
    float* s = sh[warp];

    const float* xb   = x + (size_t)b * NTOT;
    const int base0   = f0 * FS - 7;
    const int lag0    = __ldg(lags + fr0);
    const int lag1    = __ldg(lags + fr0 + 1);

    // ---- stage x windows ---------------------------------------------------
    if (f0 != 0 && f0 != 498) {                // fully in-range fast path
        const float* s0 = xb + (base0 - lag0);
        #pragma unroll
        for (int t = lane; t < 214; t += 32) s[t] = __ldg(s0 + t);
        const float* s1 = xb + (base0 + FS - lag1);
        #pragma unroll
        for (int t = lane; t < 174; t += 32) s[216 + t] = __ldg(s1 + t);
        const int lagp = __ldg(lags + fr0 - 1);
        const float* sp = xb + (base0 - lagp);
        #pragma unroll
        for (int t = lane; t < 54; t += 32) s[392 + t] = __ldg(sp + t);
    } else {                                    // f0==0 (left pads) or 498 (right pad)
        #pragma unroll
        for (int t = lane; t < 214; t += 32) {
            const int idx = base0 - lag0 + t;
            s[t] = (idx >= 0 && idx < NTOT) ? __ldg(xb + idx) : 0.f;
        }
        #pragma unroll
        for (int t = lane; t < 174; t += 32) {
            const int idx = base0 + FS - lag1 + t;
            s[216 + t] = (idx >= 0 && idx < NTOT) ? __ldg(xb + idx) : 0.f;
        }
        if (f0 != 0) {                          // f0==498: xp0 always in range
            const int lagp = __ldg(lags + fr0 - 1);
            #pragma unroll
            for (int t = lane; t < 54; t += 32) s[392 + t] = __ldg(xb + base0 - lagp + t);
        }
    }
    {   // pt: 320 floats, float4 (f0*FS is 16B aligned)
        const float4* pg = (const float4*)(xb + f0 * FS);
        float4* ps = (float4*)(s + 448);
        ps[lane]      = __ldg(pg + lane);
        ps[lane + 32] = __ldg(pg + lane + 32);
        if (lane < 16) ps[lane + 64] = __ldg(pg + lane + 64);
    }
    __syncwarp();

    const int o0 = 5 * lane;
    float res0[5], res1[5];

    // ---- frame0 main -------------------------------------------------------
    const float4* c0p = (const float4*)(g_coef + (size_t)fr0 * 16);
    const float4 c0a = __ldg(c0p), c0b = __ldg(c0p+1),
                 c0c = __ldg(c0p+2), c0d = __ldg(c0p+3);
    {
        float xv[19];
        #pragma unroll
        for (int j = 0; j < 19; j++) xv[j] = s[o0 + j];
        #pragma unroll
        for (int i = 0; i < 5; i++)
            res0[i] = c0d.w * (CONV15(xv, i, c0a, c0b, c0c, c0d) + s[448 + o0 + i]);
    }
    // ---- frame1 main -------------------------------------------------------
    const float4* c1p = (const float4*)(g_coef + (size_t)(fr0 + 1) * 16);
    const float4 c1a = __ldg(c1p), c1b = __ldg(c1p+1),
                 c1c = __ldg(c1p+2), c1d = __ldg(c1p+3);
    {
        float xv[19];
        #pragma unroll
        for (int j = 0; j < 19; j++) xv[j] = s[216 + o0 + j];
        #pragma unroll
        for (int i = 0; i < 5; i++)
            res1[i] = c1d.w * (CONV15(xv, i, c1a, c1b, c1c, c1d) + s[448 + 160 + o0 + i]);
    }

    // ---- heads (o < 40): crossfade with recomputed previous-frame tails ----
    if (lane < 8) {
        // frame1's prev tail: frame0 coefs, xc0[160..214), pass = pt[160+j]
        float t1[5];
        {
            float xw[19];
            #pragma unroll
            for (int j = 0; j < 19; j++) xw[j] = s[160 + o0 + j];
            #pragma unroll
            for (int i = 0; i < 5; i++)
                t1[i] = c0d.w * (CONV15(xw, i, c0a, c0b, c0c, c0d) + s[448 + 160 + o0 + i]);
        }
        // frame0's prev tail: coef[fr0-1], xp0, pass = pt[j]
        float t0[5] = {0.f, 0.f, 0.f, 0.f, 0.f};
        if (f0 > 0) {
            const float4* cpp = (const float4*)(g_coef + (size_t)(fr0 - 1) * 16);
            const float4 pa = __ldg(cpp), pb = __ldg(cpp+1),
                         pc = __ldg(cpp+2), pd = __ldg(cpp+3);
            float xw[19];
            #pragma unroll
            for (int j = 0; j < 19; j++) xw[j] = s[392 + o0 + j];
            #pragma unroll
            for (int i = 0; i < 5; i++)
                t0[i] = pd.w * (CONV15(xw, i, pa, pb, pc, pd) + s[448 + o0 + i]);
        }
        #pragma unroll
        for (int i = 0; i < 5; i++) {
            const float w2 = 0.5f + 0.5f * __cosf((o0 + i + 0.5f) * (PI_F / OV));
            res0[i] = res0[i] * (1.f - w2) + t0[i] * w2;   // win1 = 1 - win2
            res1[i] = res1[i] * (1.f - w2) + t1[i] * w2;
        }
    }

    // ---- bounce through shared, coalesced float4 stores --------------------
    __syncwarp();
    #pragma unroll
    for (int i = 0; i < 5; i++) {
        s[o0 + i]       = res0[i];
        s[160 + o0 + i] = res1[i];
    }
    __syncwarp();
    float4* ob = (float4*)(out + (size_t)fr0 * FS);   // out is flat [B*NF*FS]
    const float4* sb = (const float4*)s;
    ob[lane]      = sb[lane];
    ob[lane + 32] = sb[lane + 32];
    if (lane < 16) ob[lane + 64] = sb[lane + 64];
}

extern "C" void kernel_launch(void* const* d_in, const int* in_sizes, int n_in,
                              void* d_out, int out_size)
{
    const float* x        = (const float*)d_in[0];
    const float* features = (const float*)d_in[1];
    const int*   lags     = (const int*)  d_in[2];
    const float* ck_w     = (const float*)d_in[3];
    const float* ck_b     = (const float*)d_in[4];
    const float* fg_w     = (const float*)d_in[5];
    const float* fg_b     = (const float*)d_in[6];
    const float* gg_w     = (const float*)d_in[7];
    const float* gg_b     = (const float*)d_in[8];

    dots_kernel<<<NFR / 32, 64>>>(features, ck_w, ck_b, fg_w, fg_b, gg_w, gg_b);
    fir_kernel<<<NFR / 16, 256>>>(x, lags, (float*)d_out);
}

// round 12
// speedup vs baseline: 1.3425x; 1.3425x over previous
#include <cuda_runtime.h>
#include <cuda_bf16.h>
#include <math.h>

// Problem constants
#define FD      128
#define K       15
#define FS      160
#define OV      40
#define NF      500
#define BATCH   32
#define NTOT    (NF * FS)          // 80000 samples per batch row
#define NFR     (BATCH * NF)       // 16000 frames total

// C = ln(10)/20 ; LOG_GAIN_LIMIT = 10*C ; GAIN_A = 6*C ; GAIN_B = 0
#define LOG_GAIN_LIMIT 1.1512925464970229f
#define GAIN_A         0.6907755278982137f
#define PI_F           3.14159265358979323846f

// Per-frame coefficients: [0..14] = taps * gain / ||k|| (folded), [15] = ggain
__device__ __align__(16) float g_coef[NFR * 16];

// ---------------------------------------------------------------------------
// Kernel A (dots): 256-thread blocks, 8 warps, 4 frames per warp (32/block),
// grid = 500 -> 4000 warps (~27 warps/SM, latency-safe).
// Weights (17x128) staged ONCE per block into shared with a (q,seg) swizzle:
//   s_w[r*128 + q*32 + seg*4 + t] = w[r][seg*16 + q*4 + t]
// so each weight LDS.128 reads 128 CONTIGUOUS bytes across the 8 segs
// (1 wavefront, conflict-free) and is broadcast to all 4 frames.
// L1 cost drops to 17 wavefronts/frame (vs 68 in the warp-per-frame version).
// Lane layout: j = lane>>3 (frame), seg = lane&7 (16-feature segment).
// 17 register accumulators, 3 shuffle levels, in-thread epilogue.
// ---------------------------------------------------------------------------
__global__ __launch_bounds__(256)
void dots_kernel(const float* __restrict__ features,
                 const float* __restrict__ ck_w, const float* __restrict__ ck_b,
                 const float* __restrict__ fg_w, const float* __restrict__ fg_b,
                 const float* __restrict__ gg_w, const float* __restrict__ gg_b)
{
    __shared__ __align__(16) float s_w[17 * 128];        // 8.5 KB, swizzled
    const int tid  = threadIdx.x;
    const int lane = tid & 31;
    const int warp = tid >> 5;
    const int fr0  = blockIdx.x * 32 + warp * 4;         // grid = NFR/32 = 500
    const int j    = lane >> 3;                          // frame within warp
    const int seg  = lane & 7;                           // feature segment
    const int fr   = fr0 + j;

    // stage weights with swizzle: rows 0..14 = ck_w, 15 = fg_w, 16 = gg_w
    for (int o4 = tid; o4 < 544; o4 += 256) {
        const int r  = o4 >> 5;          // row 0..16
        const int c4 = o4 & 31;          // float4 column within row
        float4 v;
        if (r < 15)       v = __ldg((const float4*)ck_w + r * 32 + c4);
        else if (r == 15) v = __ldg((const float4*)fg_w + c4);
        else              v = __ldg((const float4*)gg_w + c4);
        // c = c4*4 ; seg = c4>>2 ; q = c4&3 ; dst4 = r*32 + q*8 + seg
        const int dst4 = r * 32 + (c4 & 3) * 8 + (c4 >> 2);
        *(float4*)(s_w + dst4 * 4) = v;
    }
    __syncthreads();

    // this lane's 16 features (4 float4), coalesced across the warp
    const float4* fp = (const float4*)(features + (size_t)fr * FD) + seg * 4;
    const float4 f0 = __ldg(fp + 0), f1 = __ldg(fp + 1),
                 f2 = __ldg(fp + 2), f3 = __ldg(fp + 3);

    float acc[17];
    #pragma unroll
    for (int r = 0; r < 17; r++) {
        const float4* wr = (const float4*)(s_w + r * 128) + seg;   // +q*8 below
        const float4 w0 = wr[0], w1 = wr[8], w2 = wr[16], w3 = wr[24];
        acc[r]  = f0.x*w0.x + f0.y*w0.y + f0.z*w0.z + f0.w*w0.w;
        acc[r] += f1.x*w1.x + f1.y*w1.y + f1.z*w1.z + f1.w*w1.w;
        acc[r] += f2.x*w2.x + f2.y*w2.y + f2.z*w2.z + f2.w*w2.w;
        acc[r] += f3.x*w3.x + f3.y*w3.y + f3.z*w3.z + f3.w*w3.w;
    }

    // reduce across the 8 segs of each frame (xor stays within the 8-lane group)
    #pragma unroll
    for (int r = 0; r < 17; r++) {
        acc[r] += __shfl_xor_sync(0xffffffffu, acc[r], 1);
        acc[r] += __shfl_xor_sync(0xffffffffu, acc[r], 2);
        acc[r] += __shfl_xor_sync(0xffffffffu, acc[r], 4);
    }

    // in-thread epilogue on one lane per frame
    if (seg == 0) {
        float d[15], ss = 0.f;
        #pragma unroll
        for (int r = 0; r < 15; r++) {
            d[r] = acc[r] + __ldg(ck_b + r);
            ss += d[r] * d[r];
        }
        const float fgd = acc[15] + __ldg(fg_b);
        const float ggd = acc[16] + __ldg(gg_b);
        const float gs  = __expf(LOG_GAIN_LIMIT - fmaxf(fgd, 0.f))
                        / (1e-6f + sqrtf(ss));
        const float gg  = __expf(GAIN_A * tanhf(ggd));
        float4* dst = (float4*)(g_coef + (size_t)fr * 16);
        dst[0] = make_float4(d[0]*gs,  d[1]*gs,  d[2]*gs,  d[3]*gs);
        dst[1] = make_float4(d[4]*gs,  d[5]*gs,  d[6]*gs,  d[7]*gs);
        dst[2] = make_float4(d[8]*gs,  d[9]*gs,  d[10]*gs, d[11]*gs);
        dst[3] = make_float4(d[12]*gs, d[13]*gs, d[14]*gs, gg);
    }
}

// ---------------------------------------------------------------------------
// Kernel B (fir): exact R8 version (best measured: 13.9 us).
// One warp per frame, warp-synchronous, 256-thread blocks, grid = 2000.
// Shared per warp (420 floats):
//   [  0..174)  xc : lag-gathered window, current frame
//   [174..228)  xp : lag-gathered window, prev-frame tail
//   [228..388)  pt : pass-through x[f*FS .. +160)
//   [388..404)  coefs current frame (15 taps + gg)
//   [404..420)  coefs previous frame
// ---------------------------------------------------------------------------
__global__ __launch_bounds__(256)
void fir_kernel(const float* __restrict__ x,
                const int*   __restrict__ lags,
                float*       __restrict__ out)
{
    __shared__ float sh[8][420];
    const int lane = threadIdx.x & 31;
    const int warp = threadIdx.x >> 5;
    const int fr   = blockIdx.x * 8 + warp;     // grid = NFR/8 exactly
    const int b    = fr / NF;
    const int f    = fr % NF;

    const float* xb = x + (size_t)b * NTOT;
    float* s = sh[warp];
    const int base = f * FS - 7;                // f*FS - PAD_L
    const int lag  = __ldg(lags + fr);

    // stage x windows (coalesced within the warp)
    #pragma unroll
    for (int t = lane; t < 174; t += 32) {
        const int idx = base - lag + t;
        s[t] = (idx >= 0 && idx < NTOT) ? __ldg(xb + idx) : 0.f;
    }
    if (f > 0) {
        const int lagp = __ldg(lags + fr - 1);
        #pragma unroll
        for (int t = lane; t < 54; t += 32) {
            const int idx = base - lagp + t;
            s[174 + t] = (idx >= 0) ? __ldg(xb + idx) : 0.f;
        }
    }
    #pragma unroll
    for (int t = lane; t < FS; t += 32)
        s[228 + t] = __ldg(xb + f * FS + t);

    if (lane < 16)       s[388 + lane]        = g_coef[fr * 16 + lane];
    else if (f > 0)      s[404 + (lane - 16)] = g_coef[(fr - 1) * 16 + (lane - 16)];
    __syncwarp();

    float tap[15];
    #pragma unroll
    for (int k = 0; k < 15; k++) tap[k] = s[388 + k];
    const float gg = s[403];

    float xv[19];
    #pragma unroll
    for (int j = 0; j < 19; j++) xv[j] = s[5 * lane + j];

    float res[5];
    #pragma unroll
    for (int i = 0; i < 5; i++) {
        float conv = 0.f;
        #pragma unroll
        for (int k = 0; k < 15; k++)
            conv = fmaf(xv[i + k], tap[k], conv);
        res[i] = gg * (conv + s[228 + 5 * lane + i]);
    }

    // head region o<40: crossfade with previous frame's recomputed tail
    if (lane < 8) {
        float tailv[5] = {0.f, 0.f, 0.f, 0.f, 0.f};
        if (f > 0) {
            float tp[15];
            #pragma unroll
            for (int k = 0; k < 15; k++) tp[k] = s[404 + k];
            const float ggp = s[419];
            float xpw[19];
            #pragma unroll
            for (int j = 0; j < 19; j++) xpw[j] = s[174 + 5 * lane + j];
            #pragma unroll
            for (int i = 0; i < 5; i++) {
                float cp = 0.f;
                #pragma unroll
                for (int k = 0; k < 15; k++)
                    cp = fmaf(xpw[i + k], tp[k], cp);
                // prev frame's pass-through at l=FS+j equals x[f*FS + j] = pt[j]
                tailv[i] = ggp * (cp + s[228 + 5 * lane + i]);
            }
        }
        #pragma unroll
        for (int i = 0; i < 5; i++) {
            const int j = 5 * lane + i;
            const float w2 = 0.5f + 0.5f * __cosf((j + 0.5f) * (PI_F / OV));
            res[i] = res[i] * (1.f - w2) + tailv[i] * w2;   // win1 = 1 - win2
        }
    }

    // bounce through shared (reuse xc region) for coalesced stores
    __syncwarp();
    #pragma unroll
    for (int i = 0; i < 5; i++) s[5 * lane + i] = res[i];
    __syncwarp();

    float* op = out + (size_t)b * NTOT + f * FS;
    #pragma unroll
    for (int i = 0; i < 5; i++)
        op[lane + 32 * i] = s[lane + 32 * i];
}

extern "C" void kernel_launch(void* const* d_in, const int* in_sizes, int n_in,
                              void* d_out, int out_size)
{
    const float* x        = (const float*)d_in[0];
    const float* features = (const float*)d_in[1];
    const int*   lags     = (const int*)  d_in[2];
    const float* ck_w     = (const float*)d_in[3];
    const float* ck_b     = (const float*)d_in[4];
    const float* fg_w     = (const float*)d_in[5];
    const float* fg_b     = (const float*)d_in[6];
    const float* gg_w     = (const float*)d_in[7];
    const float* gg_b     = (const float*)d_in[8];

    dots_kernel<<<NFR / 32, 256>>>(features, ck_w, ck_b, fg_w, fg_b, gg_w, gg_b);
    fir_kernel<<<NFR / 8, 256>>>(x, lags, (float*)d_out);
}